// round 1
// baseline (speedup 1.0000x reference)
#include <cuda_runtime.h>
#include <math.h>

// ---------------- static configuration ----------------
#define Bn     32
#define Tn     4096
#define Cn     3
#define NSC    128
#define NPSI   4096
#define PADL   2047
#define LP     8190           // Tn + 2*PADL
#define DXSTR  8192
#define NROW   96             // Cn * Bn
#define KSTR   3328           // >= max kernel length 3265, mult of 4
#define OUTH   224
#define OUTW   224
#define TT     1024           // conv outputs per block
#define NTHR   128
#define OUTN   (Bn*OUTH*OUTW*Cn)

// ---------------- device scratch (no allocation allowed) ----------------
__device__ float  g_dx[NROW * DXSTR];                       // 3 MB
__device__ float  g_kern[NSC * KSTR];                       // 1.7 MB
__device__ float  g_coef[(size_t)NSC * NROW * Tn];          // 192 MB
__device__ float  g_tmpA[NSC * NROW * OUTW];                // 11 MB
__device__ int    g_n[NSC];
__device__ int    g_d0[NSC];
__device__ float  g_nsq[NSC];
__device__ double g_sden[NSC];                              // s * STEP (double)
__device__ float  g_wt[OUTW * 40];
__device__ int    g_wst[OUTW];
__device__ int    g_wcnt[OUTW];
__device__ int    g_whi[OUTH * 2];
__device__ float  g_whw[OUTH * 2];

// ---------------- setup: scales, crop offsets, resize weights ----------------
__global__ void k_setup() {
    int tid = threadIdx.x;

    // per-scale metadata (replicates np.logspace(log10(2), log10(204), 128).astype(f32))
    if (tid < NSC) {
        double l2 = log10(2.0), lM = log10(204.0);
        double y = (tid == NSC - 1) ? lM : (l2 + (double)tid * ((lM - l2) / (double)(NSC - 1)));
        float  sf = (float)pow(10.0, y);
        double sd = (double)sf;
        int n = (int)ceil(sd * 16.0 + 1.0);
        int d0 = (4094 - n) / 2; if (d0 < 0) d0 = 0;
        g_n[tid]   = n;
        g_d0[tid]  = d0;
        g_nsq[tid] = -sqrtf(sf);
        g_sden[tid] = sd * (16.0 / 4095.0);                 // s * STEP
    }

    // time-axis resize weights (4096 -> 224, antialiased triangle)
    if (tid < OUTW) {
        double inv = 4096.0 / 224.0;                        // 1/scale
        double ks  = inv;                                   // kernel_scale = max(inv,1)
        double sf  = ((double)tid + 0.5) * inv - 0.5;
        int lo = (int)ceil(sf - ks);  if (lo < 0) lo = 0;
        int hi = (int)floor(sf + ks); if (hi > Tn - 1) hi = Tn - 1;
        double tot = 0.0;
        for (int i = lo; i <= hi; i++) {
            double w = 1.0 - fabs((double)i - sf) / ks; if (w < 0.0) w = 0.0;
            tot += w;
        }
        int cnt = hi - lo + 1;
        g_wst[tid] = lo; g_wcnt[tid] = cnt;
        for (int j = 0; j < cnt; j++) {
            double w = 1.0 - fabs((double)(lo + j) - sf) / ks; if (w < 0.0) w = 0.0;
            g_wt[tid * 40 + j] = (float)(w / tot);
        }
    }

    // scale-axis resize weights (128 -> 224, plain bilinear, edge-normalized)
    if (tid < OUTH) {
        double inv = 128.0 / 224.0;
        double sf  = ((double)tid + 0.5) * inv - 0.5;
        int ia = (int)floor(sf);
        int i0 = ia, i1 = ia + 1;
        double w0 = 1.0 - (sf - (double)ia);
        double w1 = sf - (double)ia;
        bool v0 = (i0 >= 0 && i0 < NSC);
        bool v1 = (i1 >= 0 && i1 < NSC);
        double tot = (v0 ? w0 : 0.0) + (v1 ? w1 : 0.0);
        int   o0 = v0 ? i0 : (v1 ? i1 : 0);
        int   o1 = v1 ? i1 : (v0 ? i0 : 0);
        float f0 = v0 ? (float)(w0 / tot) : 0.0f;
        float f1 = v1 ? (float)(w1 / tot) : 0.0f;
        if (!v0 && v1) { f0 = (float)(w1 / tot); f1 = 0.0f; }   // single-tap -> weight 1 on o0
        g_whi[tid * 2 + 0] = o0; g_whi[tid * 2 + 1] = o1;
        g_whw[tid * 2 + 0] = f0; g_whw[tid * 2 + 1] = f1;
    }
}

// ---------------- build flipped gathered kernels ----------------
__global__ void k_buildkern(const float* __restrict__ psi) {
    int sc = blockIdx.x;
    int n = g_n[sc];
    double den = g_sden[sc];
    for (int k = threadIdx.x; k < KSTR; k += blockDim.x) {
        float v = 0.0f;
        if (k < n) {
            int m = n - 1 - k;                              // flip
            double jd = floor((double)m / den);
            int j = (int)jd;
            if (j < 0) j = 0;
            if (j > NPSI - 1) j = NPSI - 1;
            v = psi[j];
        }
        g_kern[sc * KSTR + k] = v;
    }
}

// ---------------- dx = diff(reflect_pad(x)) ----------------
__device__ __forceinline__ float xp_val(const float* __restrict__ x, int b, int c, int p) {
    int i = p - PADL;
    if (i < 0) i = -i;
    else if (i >= Tn) i = 2 * (Tn - 1) - i;
    return x[((size_t)b * Tn + i) * Cn + c];
}

__global__ void k_dx(const float* __restrict__ x) {
    int idx = blockIdx.x * blockDim.x + threadIdx.x;
    if (idx >= NROW * DXSTR) return;
    int r = idx >> 13;
    int p = idx & (DXSTR - 1);
    int c = r / Bn, b = r % Bn;
    float v = 0.0f;
    if (p <= LP - 2) v = xp_val(x, b, c, p + 1) - xp_val(x, b, c, p);
    g_dx[idx] = v;
}

// ---------------- main convolution ----------------
// coef[sc,row,t] = -sqrt(s) * sum_k dx[row, d0+t+k] * kern[sc,k]
__global__ __launch_bounds__(NTHR) void k_conv() {
    __shared__ __align__(16) float sk[KSTR];
    __shared__ __align__(16) float sx[TT + KSTR + 16];

    int sc  = blockIdx.z;
    int row = blockIdx.y;
    int t0  = blockIdx.x * TT;
    int n   = g_n[sc];
    int np4 = (n + 3) & ~3;
    int d0  = g_d0[sc];
    float nsq = g_nsq[sc];

    const float* gx = g_dx + row * DXSTR + d0 + t0;
    const float* gk = g_kern + sc * KSTR;

    int xlen = TT + np4 + 4;
    for (int i = threadIdx.x; i < xlen; i += NTHR) sx[i] = gx[i];
    for (int i = threadIdx.x; i < np4;  i += NTHR) sk[i] = gk[i];
    __syncthreads();

    int oA = threadIdx.x * 4;
    int oB = oA + (TT / 2);

    float4 accA = make_float4(0.f, 0.f, 0.f, 0.f);
    float4 accB = make_float4(0.f, 0.f, 0.f, 0.f);
    const float4* sk4 = (const float4*)sk;

    float4 a0 = *(const float4*)(sx + oA);
    float4 b0 = *(const float4*)(sx + oB);

    int nq = np4 >> 2;
    #pragma unroll 2
    for (int q = 0; q < nq; q++) {
        float4 kv = sk4[q];
        float4 a1 = *(const float4*)(sx + oA + 4 * q + 4);
        float4 b1 = *(const float4*)(sx + oB + 4 * q + 4);

        accA.x += a0.x * kv.x; accA.y += a0.y * kv.x; accA.z += a0.z * kv.x; accA.w += a0.w * kv.x;
        accA.x += a0.y * kv.y; accA.y += a0.z * kv.y; accA.z += a0.w * kv.y; accA.w += a1.x * kv.y;
        accA.x += a0.z * kv.z; accA.y += a0.w * kv.z; accA.z += a1.x * kv.z; accA.w += a1.y * kv.z;
        accA.x += a0.w * kv.w; accA.y += a1.x * kv.w; accA.z += a1.y * kv.w; accA.w += a1.z * kv.w;

        accB.x += b0.x * kv.x; accB.y += b0.y * kv.x; accB.z += b0.z * kv.x; accB.w += b0.w * kv.x;
        accB.x += b0.y * kv.y; accB.y += b0.z * kv.y; accB.z += b0.w * kv.y; accB.w += b1.x * kv.y;
        accB.x += b0.z * kv.z; accB.y += b0.w * kv.z; accB.z += b1.x * kv.z; accB.w += b1.y * kv.z;
        accB.x += b0.w * kv.w; accB.y += b1.x * kv.w; accB.z += b1.y * kv.w; accB.w += b1.z * kv.w;

        a0 = a1; b0 = b1;
    }

    float* dst = g_coef + ((size_t)(sc * NROW + row)) * Tn + t0;
    float4 outA = make_float4(nsq * accA.x, nsq * accA.y, nsq * accA.z, nsq * accA.w);
    float4 outB = make_float4(nsq * accB.x, nsq * accB.y, nsq * accB.z, nsq * accB.w);
    *(float4*)(dst + oA) = outA;
    *(float4*)(dst + oB) = outB;
}

// ---------------- resize stage A: t axis 4096 -> 224 ----------------
__global__ void k_resize_t() {
    __shared__ float srow[Tn];
    int sr = blockIdx.x;                                    // sc*96 + row
    const float* src = g_coef + (size_t)sr * Tn;
    for (int i = threadIdx.x; i < Tn; i += blockDim.x) srow[i] = src[i];
    __syncthreads();
    for (int w = threadIdx.x; w < OUTW; w += blockDim.x) {
        int st = g_wst[w], cnt = g_wcnt[w];
        const float* wt = g_wt + w * 40;
        float acc = 0.0f;
        for (int j = 0; j < cnt; j++) acc += wt[j] * srow[st + j];
        g_tmpA[sr * OUTW + w] = acc;
    }
}

// ---------------- resize stage B: scale axis 128 -> 224, emit output ----------------
__global__ void k_resize_h(float* __restrict__ out) {
    int idx = blockIdx.x * blockDim.x + threadIdx.x;
    if (idx >= OUTN) return;
    int c = idx % Cn;
    int w = (idx / Cn) % OUTW;
    int h = (idx / (Cn * OUTW)) % OUTH;
    int b = idx / (Cn * OUTW * OUTH);
    int i0 = g_whi[h * 2 + 0], i1 = g_whi[h * 2 + 1];
    float f0 = g_whw[h * 2 + 0], f1 = g_whw[h * 2 + 1];
    int rb = (c * Bn + b) * OUTW + w;
    out[idx] = f0 * g_tmpA[i0 * NROW * OUTW + rb] + f1 * g_tmpA[i1 * NROW * OUTW + rb];
}

// ---------------- launch ----------------
extern "C" void kernel_launch(void* const* d_in, const int* in_sizes, int n_in,
                              void* d_out, int out_size) {
    const float* x   = (const float*)d_in[0];       // (32, 4096, 3) f32
    const float* psi = (const float*)d_in[1];       // (4096,) f32
    float* out = (float*)d_out;

    k_setup<<<1, 256>>>();
    k_buildkern<<<NSC, 256>>>(psi);
    int dxtot = NROW * DXSTR;
    k_dx<<<(dxtot + 255) / 256, 256>>>(x);
    k_conv<<<dim3(Tn / TT, NROW, NSC), NTHR>>>();
    k_resize_t<<<NSC * NROW, 256>>>();
    k_resize_h<<<(OUTN + 255) / 256, 256>>>(out);
}